// round 17
// baseline (speedup 1.0000x reference)
#include <cuda_runtime.h>
#include <cuda_fp16.h>
#include <cstdint>

// ---------------------------------------------------------------------------
// QuantizedLinear: y[t,o] = scale[o] * sum_k x[t,k]*qW[o,k] + bias[o]
// TOKENS=256, IN_F=4096, OUT_F=14336. qW int32 in [0,127) -> exact in fp16.
// R17: KC=64 (64 stages instead of 128) to halve per-stage fixed costs
// (barrier/resync/wait). 128x128 tile, fp16 m16n8k16, 2 CTAs/SM, W path
// LDG->reg magic-convert->STS in two half-rounds per stage, eager ldm,
// CTA phase stagger retained.
// ---------------------------------------------------------------------------

#define TOKENS 256
#define IN_F   4096
#define OUT_F  14336

#define M_TILE 128
#define N_TILE 128
#define KC     64                 // K elems per stage
#define NST    (IN_F / KC)        // 64 stages
#define NTHREADS 256

// Rows: 64 halfs = 128B data + 16B pad = 144B. Bank stride 36 -> each
// ldmatrix 8-row x 16B phase hits banks (4r..4r+3)+c covering all 32 once.
#define ROWB      144
#define A_STAGE_B (M_TILE * ROWB)     // 18432 (3 slots)
#define BF_BUF_B  (N_TILE * ROWB)     // 18432 (2 parity buffers)

#define SM_SCALE 0
#define SM_BIAS  512
#define SM_A0    1024
#define SM_BF0   (SM_A0 + 3 * A_STAGE_B)     // 56320
#define SM_TOTAL (SM_BF0 + 2 * BF_BUF_B)     // 93184 (x2 CTAs = 186368 OK)

__device__ __half g_x_f16[TOKENS * IN_F];

// ---------------------------------------------------------------------------
__device__ __forceinline__ uint32_t smem_u32(const void* p) {
    uint32_t a;
    asm("{ .reg .u64 t; cvta.to.shared.u64 t, %1; cvt.u32.u64 %0, t; }"
        : "=r"(a) : "l"(p));
    return a;
}

#define CP_ASYNC16(dst, src) \
    asm volatile("cp.async.cg.shared.global [%0], [%1], 16;" :: "r"(dst), "l"(src))
#define CP_COMMIT() asm volatile("cp.async.commit_group;" ::: "memory")
#define CP_WAIT(n)  asm volatile("cp.async.wait_group %0;" :: "n"(n) : "memory")

#define LDMX4(r0, r1, r2, r3, addr) \
    asm volatile("ldmatrix.sync.aligned.m8n8.x4.shared.b16 {%0,%1,%2,%3}, [%4];" \
                 : "=r"(r0), "=r"(r1), "=r"(r2), "=r"(r3) : "r"(addr))

__device__ __forceinline__ void mma_f16(float* c, const uint32_t* a, const uint32_t* b) {
    asm volatile(
        "mma.sync.aligned.m16n8k16.row.col.f32.f16.f16.f32 "
        "{%0,%1,%2,%3}, {%4,%5,%6,%7}, {%8,%9}, {%0,%1,%2,%3};"
        : "+f"(c[0]), "+f"(c[1]), "+f"(c[2]), "+f"(c[3])
        : "r"(a[0]), "r"(a[1]), "r"(a[2]), "r"(a[3]), "r"(b[0]), "r"(b[1]));
}

// Exact int(0..126) pair -> fp16x2: gather low bytes, OR 0x6400 (=1024.0,
// ULP=1 on [1024,2048)), subtract 1024. 3 ops per 2 elements.
__device__ __forceinline__ uint32_t int2_to_h2(uint32_t lo, uint32_t hi) {
    uint32_t p;
    asm("prmt.b32 %0, %1, %2, 0x5410;" : "=r"(p) : "r"(lo), "r"(hi));
    p = (p & 0x00FF00FFu) | 0x64006400u;
    uint32_t r;
    asm("sub.rn.f16x2 %0, %1, %2;" : "=r"(r) : "r"(p), "r"(0x64006400u));
    return r;
}

// ---------------------------------------------------------------------------
__global__ void __launch_bounds__(256) prep_x_kernel(const float* __restrict__ x) {
    int i = blockIdx.x * blockDim.x + threadIdx.x;   // float4 index
    const float4 v = reinterpret_cast<const float4*>(x)[i];
    __half2 h0 = __floats2half2_rn(v.x, v.y);
    __half2 h1 = __floats2half2_rn(v.z, v.w);
    uint2 p;
    p.x = *reinterpret_cast<uint32_t*>(&h0);
    p.y = *reinterpret_cast<uint32_t*>(&h1);
    reinterpret_cast<uint2*>(g_x_f16)[i] = p;
}

// ---------------------------------------------------------------------------
__global__ void __launch_bounds__(NTHREADS, 2) qlin_gemm_kernel(
    const int*   __restrict__ W,
    const float* __restrict__ scale,
    const float* __restrict__ bias,
    float*       __restrict__ out)
{
    extern __shared__ char smem[];
    const uint32_t sb = smem_u32(smem);
    const int tid = threadIdx.x;
    const int wid = tid >> 5;
    const int lid = tid & 31;
    const int g   = lid >> 2;
    const int t   = lid & 3;
    const int wm  = wid & 1;     // 2 M warp-rows (64 tokens)
    const int wn  = wid >> 1;    // 4 N warp-cols (32 feats)
    const int n0  = blockIdx.x * N_TILE;
    const int m0  = blockIdx.y * M_TILE;

    // phase stagger for co-resident CTA pair (b, b+148); output-invariant
    {
        const int bidlin = blockIdx.x + (int)gridDim.x * blockIdx.y;
        if (bidlin >= 148) {
            long long t0 = clock64();
            while (clock64() - t0 < 600) { }
        }
    }

    if (tid < N_TILE) {
        ((float*)(smem + SM_SCALE))[tid] = scale[n0 + tid];
        ((float*)(smem + SM_BIAS))[tid]  = bias[n0 + tid];
    }

    // ---- A cp.async mapping: 128 rows x 128B = 1024 x16B chunks, 4/thread --
    uint32_t aSoff[4]; const __half* aG[4];
#pragma unroll
    for (int i = 0; i < 4; i++) {
        int c = tid + i * NTHREADS;         // 0..1023
        int row = c >> 3, ca = c & 7;
        aSoff[i] = (uint32_t)(row * ROWB + ca * 16);
        aG[i]    = g_x_f16 + (size_t)(m0 + row) * IN_F + ca * 8;
    }
    // ---- W half-stage mapping: 128 rows x 32 ints (half) = 1024 x16B, 4/thr
    // fp16 out: 8B per chunk at row*ROWB + cb*8 (+64 for half1)
    uint32_t bFoff[4]; const int4* bG[4];
#pragma unroll
    for (int i = 0; i < 4; i++) {
        int c = tid + i * NTHREADS;         // 0..1023
        int row = c >> 3, cb = c & 7;
        bFoff[i] = (uint32_t)(row * ROWB + cb * 8);
        bG[i]    = reinterpret_cast<const int4*>(
                       W + (size_t)(n0 + row) * IN_F) + cb;
    }
    // int4 index per (stage, half): s*16 + half*8

    // ---- prologue ---------------------------------------------------------
#pragma unroll
    for (int s = 0; s < 2; s++) {
        const uint32_t ab = sb + SM_A0 + s * A_STAGE_B;
        const int kb = s * KC;
#pragma unroll
        for (int i = 0; i < 4; i++) CP_ASYNC16(ab + aSoff[i], aG[i] + kb);
        CP_COMMIT();
    }
    int4 wreg[4];
    {   // W(0) halves -> Bf[0]
        char* bf = smem + SM_BF0;
#pragma unroll
        for (int i = 0; i < 4; i++) wreg[i] = bG[i][0];
#pragma unroll
        for (int i = 0; i < 4; i++) {
            uint2 p;
            p.x = int2_to_h2((uint32_t)wreg[i].x, (uint32_t)wreg[i].y);
            p.y = int2_to_h2((uint32_t)wreg[i].z, (uint32_t)wreg[i].w);
            *reinterpret_cast<uint2*>(bf + bFoff[i]) = p;
        }
#pragma unroll
        for (int i = 0; i < 4; i++) wreg[i] = bG[i][8];   // stage 0 half1
#pragma unroll
        for (int i = 0; i < 4; i++) {
            uint2 p;
            p.x = int2_to_h2((uint32_t)wreg[i].x, (uint32_t)wreg[i].y);
            p.y = int2_to_h2((uint32_t)wreg[i].z, (uint32_t)wreg[i].w);
            *reinterpret_cast<uint2*>(bf + bFoff[i] + 64) = p;
        }
    }
#pragma unroll
    for (int i = 0; i < 4; i++) wreg[i] = bG[i][16];      // stage 1 half0
    CP_WAIT(1);          // A(0) arrived
    __syncthreads();     // publish Bf[0]

    float acc[4][4][4];
#pragma unroll
    for (int i = 0; i < 4; i++)
#pragma unroll
        for (int j = 0; j < 4; j++)
#pragma unroll
            for (int c = 0; c < 4; c++) acc[i][j][c] = 0.0f;

    // ---- ldmatrix bases ---------------------------------------------------
    const uint32_t aLM = sb + SM_A0 +
        (uint32_t)((wm * 64 + (lid & 7) + 8 * ((lid >> 3) & 1)) * ROWB
                   + (lid >> 4) * 16);
    const uint32_t bLM = sb + SM_BF0 +
        (uint32_t)((wn * 32 + (lid & 7) + 8 * (lid >> 4)) * ROWB
                   + ((lid >> 3) & 1) * 16);

    // ---- main loop (64 stages, 4 k16-steps each) ---------------------------
    // Invariant at top of iter s: A(s) arrived (slot s%3), A(s+1) committed,
    // Bf[s&1] published (all 4 kk), wreg = W(s+1, half0).
#pragma unroll 1
    for (int s = 0; s < NST; s++) {
        const uint32_t aS = aLM + (s % 3) * A_STAGE_B;
        const uint32_t bS = bLM + (s & 1) * BF_BUF_B;

        uint32_t aF[2][4][4], bF[2][4][2];   // two alternating frag sets

        // kk0 eager (set 0)
#pragma unroll
        for (int i = 0; i < 4; i++)
            LDMX4(aF[0][i][0], aF[0][i][1], aF[0][i][2], aF[0][i][3],
                  aS + (uint32_t)(i * 16 * ROWB));
#pragma unroll
        for (int jp = 0; jp < 2; jp++)
            LDMX4(bF[0][2*jp][0], bF[0][2*jp][1], bF[0][2*jp+1][0], bF[0][2*jp+1][1],
                  bS + (uint32_t)(jp * 16 * ROWB));

        // prefetch A(s+2); ensure A(s+1) arrived
        if (s + 2 < NST) {
            const uint32_t ab = sb + SM_A0 + ((s + 2) % 3) * A_STAGE_B;
            const int kb = (s + 2) * KC;
#pragma unroll
            for (int i = 0; i < 4; i++) CP_ASYNC16(ab + aSoff[i], aG[i] + kb);
            CP_COMMIT();
            CP_WAIT(1);
        } else {
            CP_WAIT(0);
        }

        // convert W(s+1, half0) -> Bf[(s+1)&1][0:64); LDG W(s+1, half1)
        if (s + 1 < NST) {
            char* bf = smem + SM_BF0 + ((s + 1) & 1) * BF_BUF_B;
#pragma unroll
            for (int i = 0; i < 4; i++) {
                uint2 p;
                p.x = int2_to_h2((uint32_t)wreg[i].x, (uint32_t)wreg[i].y);
                p.y = int2_to_h2((uint32_t)wreg[i].z, (uint32_t)wreg[i].w);
                *reinterpret_cast<uint2*>(bf + bFoff[i]) = p;
            }
            const int idx = (s + 1) * 16 + 8;
#pragma unroll
            for (int i = 0; i < 4; i++) wreg[i] = bG[i][idx];
        }

        // kk1 ldm (set 1); mma kk0
#pragma unroll
        for (int i = 0; i < 4; i++)
            LDMX4(aF[1][i][0], aF[1][i][1], aF[1][i][2], aF[1][i][3],
                  aS + (uint32_t)(i * 16 * ROWB) + 32);
#pragma unroll
        for (int jp = 0; jp < 2; jp++)
            LDMX4(bF[1][2*jp][0], bF[1][2*jp][1], bF[1][2*jp+1][0], bF[1][2*jp+1][1],
                  bS + (uint32_t)(jp * 16 * ROWB) + 32);
#pragma unroll
        for (int i = 0; i < 4; i++)
#pragma unroll
            for (int j = 0; j < 4; j++)
                mma_f16(acc[i][j], aF[0][i], bF[0][j]);

        // kk2 ldm (set 0); mma kk1
#pragma unroll
        for (int i = 0; i < 4; i++)
            LDMX4(aF[0][i][0], aF[0][i][1], aF[0][i][2], aF[0][i][3],
                  aS + (uint32_t)(i * 16 * ROWB) + 64);
#pragma unroll
        for (int jp = 0; jp < 2; jp++)
            LDMX4(bF[0][2*jp][0], bF[0][2*jp][1], bF[0][2*jp+1][0], bF[0][2*jp+1][1],
                  bS + (uint32_t)(jp * 16 * ROWB) + 64);
#pragma unroll
        for (int i = 0; i < 4; i++)
#pragma unroll
            for (int j = 0; j < 4; j++)
                mma_f16(acc[i][j], aF[1][i], bF[1][j]);

        // convert W(s+1, half1) -> Bf[(s+1)&1][64:128); LDG W(s+2, half0)
        if (s + 1 < NST) {
            char* bf = smem + SM_BF0 + ((s + 1) & 1) * BF_BUF_B;
#pragma unroll
            for (int i = 0; i < 4; i++) {
                uint2 p;
                p.x = int2_to_h2((uint32_t)wreg[i].x, (uint32_t)wreg[i].y);
                p.y = int2_to_h2((uint32_t)wreg[i].z, (uint32_t)wreg[i].w);
                *reinterpret_cast<uint2*>(bf + bFoff[i] + 64) = p;
            }
        }
        if (s + 2 < NST) {
            const int idx = (s + 2) * 16;
#pragma unroll
            for (int i = 0; i < 4; i++) wreg[i] = bG[i][idx];
        }

        // kk3 ldm (set 1); mma kk2; mma kk3
#pragma unroll
        for (int i = 0; i < 4; i++)
            LDMX4(aF[1][i][0], aF[1][i][1], aF[1][i][2], aF[1][i][3],
                  aS + (uint32_t)(i * 16 * ROWB) + 96);
#pragma unroll
        for (int jp = 0; jp < 2; jp++)
            LDMX4(bF[1][2*jp][0], bF[1][2*jp][1], bF[1][2*jp+1][0], bF[1][2*jp+1][1],
                  bS + (uint32_t)(jp * 16 * ROWB) + 96);
#pragma unroll
        for (int i = 0; i < 4; i++)
#pragma unroll
            for (int j = 0; j < 4; j++)
                mma_f16(acc[i][j], aF[0][i], bF[0][j]);
#pragma unroll
        for (int i = 0; i < 4; i++)
#pragma unroll
            for (int j = 0; j < 4; j++)
                mma_f16(acc[i][j], aF[1][i], bF[1][j]);

        __syncthreads();   // publishes Bf[(s+1)&1] + guards A-slot reuse
    }

    // ---- epilogue ---------------------------------------------------------
    const float* s_sc = (const float*)(smem + SM_SCALE);
    const float* s_bi = (const float*)(smem + SM_BIAS);
#pragma unroll
    for (int i = 0; i < 4; i++) {
        const int m = m0 + wm * 64 + i * 16 + g;
#pragma unroll
        for (int j = 0; j < 4; j++) {
            const int nl = wn * 32 + j * 8 + 2 * t;
            const float sc0 = s_sc[nl],     bi0 = s_bi[nl];
            const float sc1 = s_sc[nl + 1], bi1 = s_bi[nl + 1];
            float2 v0 = { acc[i][j][0] * sc0 + bi0, acc[i][j][1] * sc1 + bi1 };
            float2 v1 = { acc[i][j][2] * sc0 + bi0, acc[i][j][3] * sc1 + bi1 };
            *reinterpret_cast<float2*>(out + (size_t)m * OUT_F + n0 + nl) = v0;
            *reinterpret_cast<float2*>(out + (size_t)(m + 8) * OUT_F + n0 + nl) = v1;
        }
    }
}

// ---------------------------------------------------------------------------
extern "C" void kernel_launch(void* const* d_in, const int* in_sizes, int n_in,
                              void* d_out, int out_size) {
    const float* x     = (const float*)d_in[0];
    const int*   W     = (const int*)  d_in[1];
    const float* scale = (const float*)d_in[2];
    const float* bias  = (const float*)d_in[3];
    float*       out   = (float*)d_out;

    (void)in_sizes; (void)n_in; (void)out_size;

    cudaFuncSetAttribute(qlin_gemm_kernel,
                         cudaFuncAttributeMaxDynamicSharedMemorySize, SM_TOTAL);

    prep_x_kernel<<<(TOKENS * IN_F / 4) / 256, 256>>>(x);

    dim3 grid(OUT_F / N_TILE, TOKENS / M_TILE);   // (112, 2) -> 2 CTAs/SM
    qlin_gemm_kernel<<<grid, NTHREADS, SM_TOTAL>>>(W, scale, bias, out);
}